// round 8
// baseline (speedup 1.0000x reference)
#include <cuda_runtime.h>

// Problem: B=1, L=768, D_SINGLE=384, D_PAIR=128
//   left  = s @ W[:384] + bias   (768x128)   [bias folded into left]
//   right = s @ W[384:]          (768x128)
//   out[i,j,f] = left[i,f] + right[j,f]      -> 768*768*128 fp32 = 302 MB
//
// R8 (= R7 fixed): eviction-priority split. Rows i < PERSIST_ROWS stored with
// st.global.L2::evict_last.v8.b32 (sm_103a requires 256-bit for evict_last) —
// that slice stays L2-resident across graph replays and is re-dirtied in place.
// Remaining rows use __stcs (evict_first) so the streaming portion self-evicts
// and never displaces the pinned slice.
//
// Inputs (metadata order): s (768*384 f32), z (UNUSED), W (768*128 f32), bias (128 f32)

#define L_DIM 768
#define DS 384
#define DP 128
#define TI 6                 // rows per proj block -> 128 blocks (single wave)
#define PERSIST_ROWS 200     // 200 * 768*128*4B = 78.6 MB pinned (< 126 MB L2)

// scratch (no cudaMalloc allowed)
__device__ float g_left[L_DIM * DP];    // includes bias
__device__ float g_right[L_DIM * DP];

// ---------------------------------------------------------------------------
// Kernel 1: projections. 128 blocks x 256 threads. (R5 best, unchanged)
// ---------------------------------------------------------------------------
__global__ __launch_bounds__(256) void proj_kernel(
    const float* __restrict__ s,     // [768, 384]
    const float* __restrict__ W,     // [768, 128]
    const float* __restrict__ bias)  // [128]
{
    __shared__ float s_sh[TI][DS];
    const int i0  = blockIdx.x * TI;
    const int tid = threadIdx.x;

    for (int idx = tid; idx < TI * DS; idx += 256) {
        int r = idx / DS, c = idx % DS;
        s_sh[r][c] = s[(size_t)(i0 + r) * DS + c];
    }
    __syncthreads();

    const int f    = tid & 127;
    const int half = tid >> 7;                    // 0 = left, 1 = right
    const float* Wcol = W + (size_t)(half ? DS : 0) * DP + f;

    float acc[TI];
#pragma unroll
    for (int ii = 0; ii < TI; ii++) acc[ii] = 0.f;

    const float4 (*s4)[DS / 4] = reinterpret_cast<const float4 (*)[DS / 4]>(s_sh);

#pragma unroll 4
    for (int k4 = 0; k4 < DS / 4; k4++) {
        const int kb = k4 * 4;
        float w0 = Wcol[(size_t)(kb + 0) * DP];
        float w1 = Wcol[(size_t)(kb + 1) * DP];
        float w2 = Wcol[(size_t)(kb + 2) * DP];
        float w3 = Wcol[(size_t)(kb + 3) * DP];
#pragma unroll
        for (int ii = 0; ii < TI; ii++) {
            float4 sv = s4[ii][k4];               // one LDS.128, warp-broadcast
            acc[ii] = fmaf(sv.x, w0, acc[ii]);
            acc[ii] = fmaf(sv.y, w1, acc[ii]);
            acc[ii] = fmaf(sv.z, w2, acc[ii]);
            acc[ii] = fmaf(sv.w, w3, acc[ii]);
        }
    }

    if (half == 0) {
        const float b = bias[f];
#pragma unroll
        for (int ii = 0; ii < TI; ii++)
            g_left[(size_t)(i0 + ii) * DP + f] = acc[ii] + b;
    } else {
#pragma unroll
        for (int ii = 0; ii < TI; ii++)
            g_right[(size_t)(i0 + ii) * DP + f] = acc[ii];
    }

    __syncthreads();
    __threadfence();
    cudaTriggerProgrammaticLaunchCompletion();
}

// ---------------------------------------------------------------------------
// 256-bit evict_last store (required width for evict_last on sm_103a)
// ---------------------------------------------------------------------------
__device__ __forceinline__ void st_evict_last_256(void* p, float4 a, float4 b) {
    asm volatile(
        "st.global.L2::evict_last.v8.b32 [%0], {%1,%2,%3,%4,%5,%6,%7,%8};"
        :: "l"(p),
           "r"(__float_as_uint(a.x)), "r"(__float_as_uint(a.y)),
           "r"(__float_as_uint(a.z)), "r"(__float_as_uint(a.w)),
           "r"(__float_as_uint(b.x)), "r"(__float_as_uint(b.y)),
           "r"(__float_as_uint(b.z)), "r"(__float_as_uint(b.w))
        : "memory");
}

// ---------------------------------------------------------------------------
// Kernel 2: broadcast-add with split eviction policy.
// ---------------------------------------------------------------------------
__global__ __launch_bounds__(256) void bcast_kernel(float* __restrict__ out)
{
    const int i   = blockIdx.y;
    const int j0  = blockIdx.x * 128;
    const int tid = threadIdx.x;

    cudaGridDependencySynchronize();   // PDL: wait for proj's triggered stores

    const float4* left4  = reinterpret_cast<const float4*>(g_left);
    const float4* right4 = reinterpret_cast<const float4*>(g_right);
    float4* out4 = reinterpret_cast<float4*>(out);

    if (i < PERSIST_ROWS) {
        // Pinned slice: 32-byte evict_last stores.
        // 16 threads cover one 128-float row (8 floats each), 16 j rows in parallel.
        const int f8 = tid & 15;           // 8-float group
        const int jl = tid >> 4;           // 0..15
        const float4 lv0 = left4[(size_t)i * 32 + f8 * 2 + 0];
        const float4 lv1 = left4[(size_t)i * 32 + f8 * 2 + 1];
        const size_t orow = ((size_t)i * L_DIM + j0) * 32 + f8 * 2;

#pragma unroll 4
        for (int jj = jl; jj < 128; jj += 16) {
            float4 r0 = __ldg(right4 + (size_t)(j0 + jj) * 32 + f8 * 2 + 0);
            float4 r1 = __ldg(right4 + (size_t)(j0 + jj) * 32 + f8 * 2 + 1);
            float4 a, b;
            a.x = lv0.x + r0.x; a.y = lv0.y + r0.y;
            a.z = lv0.z + r0.z; a.w = lv0.w + r0.w;
            b.x = lv1.x + r1.x; b.y = lv1.y + r1.y;
            b.z = lv1.z + r1.z; b.w = lv1.w + r1.w;
            st_evict_last_256(out4 + orow + (size_t)jj * 32, a, b);
        }
    } else {
        // Streaming slice: evict-first float4 stores, drains to DRAM.
        const int f4 = tid & 31;
        const int jl = tid >> 5;
        const float4 lv = left4[(size_t)i * 32 + f4];
        const size_t orow = ((size_t)i * L_DIM + j0) * 32 + f4;

#pragma unroll 4
        for (int jj = jl; jj < 128; jj += 8) {
            float4 rv = __ldg(right4 + (size_t)(j0 + jj) * 32 + f4);
            float4 o;
            o.x = lv.x + rv.x;
            o.y = lv.y + rv.y;
            o.z = lv.z + rv.z;
            o.w = lv.w + rv.w;
            __stcs(out4 + orow + (size_t)jj * 32, o);
        }
    }
}

// ---------------------------------------------------------------------------
extern "C" void kernel_launch(void* const* d_in, const int* in_sizes, int n_in,
                              void* d_out, int out_size)
{
    const float* s    = (const float*)d_in[0];
    // d_in[1] = z : intentionally unused (reference never reads it)
    const float* W    = (const float*)d_in[2];
    const float* bias = (const float*)d_in[3];
    float* out = (float*)d_out;

    proj_kernel<<<L_DIM / TI, 256>>>(s, W, bias);

    cudaLaunchConfig_t cfg = {};
    cfg.gridDim  = dim3(L_DIM / 128, L_DIM);   // (6, 768)
    cfg.blockDim = dim3(256, 1, 1);
    cfg.dynamicSmemBytes = 0;
    cfg.stream = 0;

    cudaLaunchAttribute attr;
    attr.id = cudaLaunchAttributeProgrammaticStreamSerialization;
    attr.val.programmaticStreamSerializationAllowed = 1;
    cfg.attrs = &attr;
    cfg.numAttrs = 1;

    cudaLaunchKernelEx(&cfg, bcast_kernel, out);
}

// round 9
// speedup vs baseline: 1.1973x; 1.1973x over previous
#include <cuda_runtime.h>

// Problem: B=1, L=768, D_SINGLE=384, D_PAIR=128
//   left  = s @ W[:384] + bias   (768x128)   [bias folded into left]
//   right = s @ W[384:]          (768x128)
//   out[i,j,f] = left[i,f] + right[j,f]      -> 768*768*128 fp32 = 302 MB
//
// R9: multi-i tiled bcast. Each block handles TI_B=8 i-rows x one 128-j chunk:
// one L2 read of right[j] now feeds 8 output rows (L2 read traffic 295->37 MB,
// L1 wavefront pressure way down). Store policy: pure __stcs evict-first
// (R6/R8 proved any retention policy costs +20us). PDL chaining kept from R5.
//
// Inputs (metadata order): s (768*384 f32), z (UNUSED), W (768*128 f32), bias (128 f32)

#define L_DIM 768
#define DS 384
#define DP 128
#define TI 6          // rows per proj block -> 128 blocks (single wave)
#define TI_B 8        // i-rows per bcast block

// scratch (no cudaMalloc allowed)
__device__ float g_left[L_DIM * DP];    // includes bias
__device__ float g_right[L_DIM * DP];

// ---------------------------------------------------------------------------
// Kernel 1: projections. 128 blocks x 256 threads. (R5 best, unchanged)
// ---------------------------------------------------------------------------
__global__ __launch_bounds__(256) void proj_kernel(
    const float* __restrict__ s,     // [768, 384]
    const float* __restrict__ W,     // [768, 128]
    const float* __restrict__ bias)  // [128]
{
    __shared__ float s_sh[TI][DS];
    const int i0  = blockIdx.x * TI;
    const int tid = threadIdx.x;

    for (int idx = tid; idx < TI * DS; idx += 256) {
        int r = idx / DS, c = idx % DS;
        s_sh[r][c] = s[(size_t)(i0 + r) * DS + c];
    }
    __syncthreads();

    const int f    = tid & 127;
    const int half = tid >> 7;                    // 0 = left, 1 = right
    const float* Wcol = W + (size_t)(half ? DS : 0) * DP + f;

    float acc[TI];
#pragma unroll
    for (int ii = 0; ii < TI; ii++) acc[ii] = 0.f;

    const float4 (*s4)[DS / 4] = reinterpret_cast<const float4 (*)[DS / 4]>(s_sh);

#pragma unroll 4
    for (int k4 = 0; k4 < DS / 4; k4++) {
        const int kb = k4 * 4;
        float w0 = Wcol[(size_t)(kb + 0) * DP];
        float w1 = Wcol[(size_t)(kb + 1) * DP];
        float w2 = Wcol[(size_t)(kb + 2) * DP];
        float w3 = Wcol[(size_t)(kb + 3) * DP];
#pragma unroll
        for (int ii = 0; ii < TI; ii++) {
            float4 sv = s4[ii][k4];               // one LDS.128, warp-broadcast
            acc[ii] = fmaf(sv.x, w0, acc[ii]);
            acc[ii] = fmaf(sv.y, w1, acc[ii]);
            acc[ii] = fmaf(sv.z, w2, acc[ii]);
            acc[ii] = fmaf(sv.w, w3, acc[ii]);
        }
    }

    if (half == 0) {
        const float b = bias[f];
#pragma unroll
        for (int ii = 0; ii < TI; ii++)
            g_left[(size_t)(i0 + ii) * DP + f] = acc[ii] + b;
    } else {
#pragma unroll
        for (int ii = 0; ii < TI; ii++)
            g_right[(size_t)(i0 + ii) * DP + f] = acc[ii];
    }

    __syncthreads();
    __threadfence();
    cudaTriggerProgrammaticLaunchCompletion();
}

// ---------------------------------------------------------------------------
// Kernel 2: broadcast-add, 8 i-rows per block.
// grid = (6 j-chunks, 96 i-tiles). 256 threads: f4 = tid&31, jl = tid>>5.
// One right[j] float4 read -> 8 output stores.
// ---------------------------------------------------------------------------
__global__ __launch_bounds__(256) void bcast_kernel(float* __restrict__ out)
{
    const int i0  = blockIdx.y * TI_B;
    const int j0  = blockIdx.x * 128;
    const int tid = threadIdx.x;
    const int f4  = tid & 31;
    const int jl  = tid >> 5;

    cudaGridDependencySynchronize();   // PDL: wait for proj's triggered stores

    const float4* left4  = reinterpret_cast<const float4*>(g_left);
    const float4* right4 = reinterpret_cast<const float4*>(g_right);
    float4* out4 = reinterpret_cast<float4*>(out);

    float4 lv[TI_B];
#pragma unroll
    for (int ii = 0; ii < TI_B; ii++)
        lv[ii] = left4[(size_t)(i0 + ii) * 32 + f4];    // includes bias

    const size_t obase = ((size_t)i0 * L_DIM + j0) * 32 + f4;

#pragma unroll 2
    for (int jj = jl; jj < 128; jj += 8) {
        float4 rv = __ldg(right4 + (size_t)(j0 + jj) * 32 + f4);
        const size_t ocol = obase + (size_t)jj * 32;
#pragma unroll
        for (int ii = 0; ii < TI_B; ii++) {
            float4 o;
            o.x = lv[ii].x + rv.x;
            o.y = lv[ii].y + rv.y;
            o.z = lv[ii].z + rv.z;
            o.w = lv[ii].w + rv.w;
            __stcs(out4 + ocol + (size_t)ii * (L_DIM * 32), o);  // evict-first
        }
    }
}

// ---------------------------------------------------------------------------
extern "C" void kernel_launch(void* const* d_in, const int* in_sizes, int n_in,
                              void* d_out, int out_size)
{
    const float* s    = (const float*)d_in[0];
    // d_in[1] = z : intentionally unused (reference never reads it)
    const float* W    = (const float*)d_in[2];
    const float* bias = (const float*)d_in[3];
    float* out = (float*)d_out;

    proj_kernel<<<L_DIM / TI, 256>>>(s, W, bias);

    cudaLaunchConfig_t cfg = {};
    cfg.gridDim  = dim3(L_DIM / 128, L_DIM / TI_B);   // (6, 96)
    cfg.blockDim = dim3(256, 1, 1);
    cfg.dynamicSmemBytes = 0;
    cfg.stream = 0;

    cudaLaunchAttribute attr;
    attr.id = cudaLaunchAttributeProgrammaticStreamSerialization;
    attr.val.programmaticStreamSerializationAllowed = 1;
    cfg.attrs = &attr;
    cfg.numAttrs = 1;

    cudaLaunchKernelEx(&cfg, bcast_kernel, out);
}